// round 5
// baseline (speedup 1.0000x reference)
#include <cuda_runtime.h>
#include <cuda_bf16.h>
#include <cstdint>

#define B_  2
#define S_  2048
#define H_  2048
#define NH  16
#define HD  128
#define M_  (B_*S_)
#define NQ  (S_/128)

// Single shared-memory symbol for the whole TU
extern __shared__ __align__(16) unsigned char sm_raw[];

// ---------------------------------------------------------------------------
// Scratch
// ---------------------------------------------------------------------------
__device__ __nv_bfloat16 g_xhi[(size_t)M_*H_];
__device__ __nv_bfloat16 g_xlo[(size_t)M_*H_];
__device__ __nv_bfloat16 g_whi[4][(size_t)H_*H_];
__device__ __nv_bfloat16 g_wlo[4][(size_t)H_*H_];
__device__ __nv_bfloat16 g_qhi[(size_t)M_*H_];   // [b,h,s,d], pre-scaled
__device__ __nv_bfloat16 g_qlo[(size_t)M_*H_];
__device__ __nv_bfloat16 g_khi[(size_t)M_*H_];   // [b,h,s,d]
__device__ __nv_bfloat16 g_klo[(size_t)M_*H_];
__device__ __nv_bfloat16 g_vthi[(size_t)M_*H_];  // [b,h,d,s] (transposed)
__device__ __nv_bfloat16 g_vtlo[(size_t)M_*H_];
__device__ __nv_bfloat16 g_chi[(size_t)M_*H_];   // [b,s,h]
__device__ __nv_bfloat16 g_clo[(size_t)M_*H_];

// ---------------------------------------------------------------------------
__global__ void split_bf16(const float* __restrict__ in,
                           __nv_bfloat16* __restrict__ hi,
                           __nv_bfloat16* __restrict__ lo, int n4)
{
    int i = blockIdx.x * blockDim.x + threadIdx.x;
    int stride = gridDim.x * blockDim.x;
    for (; i < n4; i += stride) {
        float4 v = ((const float4*)in)[i];
        __nv_bfloat16 h0 = __float2bfloat16(v.x);
        __nv_bfloat16 h1 = __float2bfloat16(v.y);
        __nv_bfloat16 h2 = __float2bfloat16(v.z);
        __nv_bfloat16 h3 = __float2bfloat16(v.w);
        __nv_bfloat162* hp = (__nv_bfloat162*)hi;
        __nv_bfloat162* lp = (__nv_bfloat162*)lo;
        hp[2*i+0] = __nv_bfloat162(h0, h1);
        hp[2*i+1] = __nv_bfloat162(h2, h3);
        lp[2*i+0] = __nv_bfloat162(__float2bfloat16(v.x - __bfloat162float(h0)),
                                   __float2bfloat16(v.y - __bfloat162float(h1)));
        lp[2*i+1] = __nv_bfloat162(__float2bfloat16(v.z - __bfloat162float(h2)),
                                   __float2bfloat16(v.w - __bfloat162float(h3)));
    }
}

// ---------------------------------------------------------------------------
// PTX helpers
// ---------------------------------------------------------------------------
__device__ __forceinline__ uint32_t smem_u32(const void* p) {
    uint32_t a;
    asm("{ .reg .u64 t; cvta.to.shared.u64 t, %1; cvt.u32.u64 %0, t; }" : "=r"(a) : "l"(p));
    return a;
}
__device__ __forceinline__ void cp16(uint32_t s, const void* g) {
    asm volatile("cp.async.cg.shared.global [%0], [%1], 16;\n" :: "r"(s), "l"(g));
}
__device__ __forceinline__ void cp_commit() { asm volatile("cp.async.commit_group;\n"); }
template<int N> __device__ __forceinline__ void cp_wait() {
    asm volatile("cp.async.wait_group %0;\n" :: "n"(N));
}
__device__ __forceinline__ void mma16816(float* d, const uint32_t* a, const uint32_t* b) {
    asm volatile("mma.sync.aligned.m16n8k16.row.col.f32.bf16.bf16.f32 "
                 "{%0,%1,%2,%3}, {%4,%5,%6,%7}, {%8,%9}, {%0,%1,%2,%3};\n"
                 : "+f"(d[0]), "+f"(d[1]), "+f"(d[2]), "+f"(d[3])
                 : "r"(a[0]), "r"(a[1]), "r"(a[2]), "r"(a[3]), "r"(b[0]), "r"(b[1]));
}
__device__ __forceinline__ uint32_t packbf(float a, float b) {
    __nv_bfloat162 h(__float2bfloat16(a), __float2bfloat16(b));
    return *(uint32_t*)&h;
}

// ---------------------------------------------------------------------------
// bf16x3 GEMM (NT): C = A * W^T + bias.  MODE 0: hi/lo [b,h,s,d] (* scale)
// MODE 1: fp32 [M,N].  MODE 2: hi/lo transposed [b,h,d,s].
// ---------------------------------------------------------------------------
#define GSTRIDE 40
#define TILE_ELEMS (128*GSTRIDE)
#define STAGE_ELEMS (4*TILE_ELEMS)
#define GEMM_SMEM_BYTES (2*STAGE_ELEMS*2)

template<int MODE>
__global__ __launch_bounds__(256) void gemm_bf16x3(
    const __nv_bfloat16* __restrict__ Ahi, const __nv_bfloat16* __restrict__ Alo,
    const __nv_bfloat16* __restrict__ Whi, const __nv_bfloat16* __restrict__ Wlo,
    const float* __restrict__ bias, float scale,
    float* __restrict__ outf,
    __nv_bfloat16* __restrict__ outhi, __nv_bfloat16* __restrict__ outlo)
{
    __nv_bfloat16* sm = (__nv_bfloat16*)sm_raw;
    const int K = H_;
    const int tid  = threadIdx.x;
    const int lane = tid & 31, warp = tid >> 5;
    const int g = lane >> 2, tg = lane & 3;
    const int wm = (warp >> 2) * 64, wn = (warp & 3) * 32;
    const int bm = blockIdx.y * 128, bn = blockIdx.x * 128;

    const uint32_t sbase = smem_u32(sm);
    const int lrow0 = tid >> 2;
    const int lc8   = (tid & 3) * 8;
    const __nv_bfloat16* gA = Ahi + (size_t)(bm + lrow0) * K + lc8;
    const __nv_bfloat16* gAl= Alo + (size_t)(bm + lrow0) * K + lc8;
    const __nv_bfloat16* gW = Whi + (size_t)(bn + lrow0) * K + lc8;
    const __nv_bfloat16* gWl= Wlo + (size_t)(bn + lrow0) * K + lc8;
    const uint32_t soff0 = (uint32_t)(lrow0 * GSTRIDE + lc8) * 2;
    const uint32_t srowadd = 64 * GSTRIDE * 2;

    auto issue = [&](int kt, int buf) {
        const int k0 = kt * 32;
        uint32_t sb = sbase + buf * (STAGE_ELEMS * 2);
        #pragma unroll
        for (int t = 0; t < 2; t++) {
            uint32_t so = soff0 + t * srowadd;
            size_t go = (size_t)t * 64 * K + k0;
            cp16(sb + 0*TILE_ELEMS*2 + so, gA  + go);
            cp16(sb + 1*TILE_ELEMS*2 + so, gAl + go);
            cp16(sb + 2*TILE_ELEMS*2 + so, gW  + go);
            cp16(sb + 3*TILE_ELEMS*2 + so, gWl + go);
        }
        cp_commit();
    };

    float acc[4][4][4] = {};
    issue(0, 0);
    issue(1, 1);

    const int NT = K / 32;
    for (int kt = 0; kt < NT; kt++) {
        if (kt < NT - 1) cp_wait<1>(); else cp_wait<0>();
        __syncthreads();

        const __nv_bfloat16* As  = sm + (kt & 1) * STAGE_ELEMS;
        const __nv_bfloat16* Als = As + TILE_ELEMS;
        const __nv_bfloat16* Bs  = As + 2 * TILE_ELEMS;
        const __nv_bfloat16* Bls = As + 3 * TILE_ELEMS;

        #pragma unroll
        for (int kh = 0; kh < 32; kh += 16) {
            const int ac = kh + 2 * tg;
            uint32_t af[4][4], bh[4][2], bl[4][2];
            #pragma unroll
            for (int mi = 0; mi < 4; mi++) {
                const int r = (wm + mi * 16 + g) * GSTRIDE + ac;
                af[mi][0] = *(const uint32_t*)&As[r];
                af[mi][1] = *(const uint32_t*)&As[r + 8 * GSTRIDE];
                af[mi][2] = *(const uint32_t*)&As[r + 8];
                af[mi][3] = *(const uint32_t*)&As[r + 8 * GSTRIDE + 8];
            }
            #pragma unroll
            for (int ni = 0; ni < 4; ni++) {
                const int r = (wn + ni * 8 + g) * GSTRIDE + ac;
                bh[ni][0] = *(const uint32_t*)&Bs[r];
                bh[ni][1] = *(const uint32_t*)&Bs[r + 8];
            }
            #pragma unroll
            for (int mi = 0; mi < 4; mi++)
                #pragma unroll
                for (int ni = 0; ni < 4; ni++)
                    mma16816(acc[mi][ni], af[mi], bh[ni]);
            #pragma unroll
            for (int ni = 0; ni < 4; ni++) {
                const int r = (wn + ni * 8 + g) * GSTRIDE + ac;
                bl[ni][0] = *(const uint32_t*)&Bls[r];
                bl[ni][1] = *(const uint32_t*)&Bls[r + 8];
            }
            #pragma unroll
            for (int mi = 0; mi < 4; mi++)
                #pragma unroll
                for (int ni = 0; ni < 4; ni++)
                    mma16816(acc[mi][ni], af[mi], bl[ni]);
            #pragma unroll
            for (int mi = 0; mi < 4; mi++) {
                const int r = (wm + mi * 16 + g) * GSTRIDE + ac;
                af[mi][0] = *(const uint32_t*)&Als[r];
                af[mi][1] = *(const uint32_t*)&Als[r + 8 * GSTRIDE];
                af[mi][2] = *(const uint32_t*)&Als[r + 8];
                af[mi][3] = *(const uint32_t*)&Als[r + 8 * GSTRIDE + 8];
            }
            #pragma unroll
            for (int mi = 0; mi < 4; mi++)
                #pragma unroll
                for (int ni = 0; ni < 4; ni++)
                    mma16816(acc[mi][ni], af[mi], bh[ni]);
        }
        __syncthreads();
        if (kt + 2 < NT) issue(kt + 2, kt & 1);
    }

    // epilogue
    #pragma unroll
    for (int ni = 0; ni < 4; ni++) {
        const int n0 = bn + wn + ni * 8 + 2 * tg;
        const float b0 = bias[n0], b1 = bias[n0 + 1];
        #pragma unroll
        for (int mi = 0; mi < 4; mi++) {
            #pragma unroll
            for (int h = 0; h < 2; h++) {
                const int row = bm + wm + mi * 16 + g + h * 8;
                float vx = acc[mi][ni][2*h+0] + b0;
                float vy = acc[mi][ni][2*h+1] + b1;
                if (MODE == 1) {
                    *(float2*)(outf + (size_t)row * H_ + n0) = make_float2(vx, vy);
                } else {
                    if (MODE == 0) { vx *= scale; vy *= scale; }
                    __nv_bfloat16 hx = __float2bfloat16(vx);
                    __nv_bfloat16 hy = __float2bfloat16(vy);
                    __nv_bfloat16 lx = __float2bfloat16(vx - __bfloat162float(hx));
                    __nv_bfloat16 ly = __float2bfloat16(vy - __bfloat162float(hy));
                    const int b  = row >> 11;
                    const int s  = row & 2047;
                    const int hd = n0 >> 7;
                    const int dd = n0 & 127;
                    if (MODE == 0) {
                        size_t idx = ((size_t)(b * NH + hd) * S_ + s) * HD + dd;
                        __nv_bfloat162 vh(hx, hy), vl(lx, ly);
                        *(__nv_bfloat162*)(outhi + idx) = vh;
                        *(__nv_bfloat162*)(outlo + idx) = vl;
                    } else { // MODE 2: transposed [b,h,d,s]
                        size_t idx = ((size_t)(b * NH + hd) * HD + dd) * S_ + s;
                        outhi[idx]      = hx;  outhi[idx + S_] = hy;
                        outlo[idx]      = lx;  outlo[idx + S_] = ly;
                    }
                }
            }
        }
    }
}

// ---------------------------------------------------------------------------
// Flash attention v2: 512 threads (16 warps), BR=128, BC=64.
// Warp w: wq=w&7 (row group: rows q0+wq*16..+15), wc=w>>3 (column half:
// cols wc*32..+31 of each 64-col tile). Cross-warp softmax: per-iter exchange
// of row maxima via smem; l and O kept as per-warp partials, combined at end.
// K double-buffered, V single-buffered (cp.async group ordering keeps K one
// tile ahead). smem 174KB -> 1 CTA/SM but 16 warps (4/SMSP).
// Offsets in bf16 elems unless noted:
//   Q hi 0, lo 17408 (128 x 136)
//   K stage st: 34816 + st*17408 (hi 64x136, lo +8704)
//   V: hi 69632, lo 78848 (128 x 72)
//   float scratch: pmax @f44032 (8 pairs x 2 x 16), lsm @f44288 (128)
//   epilogue O partial overlays Q/K region (float idx 0, stride 130)
// ---------------------------------------------------------------------------
#define FL2_QHI 0
#define FL2_QLO 17408
#define FL2_KOF(st) (34816 + (st)*17408)
#define FL2_VHI 69632
#define FL2_VLO 78848
#define FL2_PMAXF 44032
#define FL2_LSMF  44288
#define FL2_SMEM_BYTES 177664

__global__ __launch_bounds__(512, 1) void flash_attn_v2(
    const __nv_bfloat16* __restrict__ Qhi, const __nv_bfloat16* __restrict__ Qlo,
    const __nv_bfloat16* __restrict__ Khi, const __nv_bfloat16* __restrict__ Klo,
    const __nv_bfloat16* __restrict__ VThi, const __nv_bfloat16* __restrict__ VTlo,
    __nv_bfloat16* __restrict__ Chi, __nv_bfloat16* __restrict__ Clo)
{
    __nv_bfloat16* sm = (__nv_bfloat16*)sm_raw;
    float* smf = (float*)sm_raw;
    const int tid = threadIdx.x, lane = tid & 31, w = tid >> 5;
    const int g = lane >> 2, tg = lane & 3;
    const int wq = w & 7, wc = w >> 3;
    const int bh = blockIdx.y, b = bh >> 4, head = bh & 15;
    const int q0 = (NQ - 1 - (int)blockIdx.x) * 128;   // heavy blocks first
    const size_t base  = (size_t)bh * S_ * HD;
    const size_t vbase = (size_t)bh * HD * S_;
    const uint32_t sb = smem_u32(sm);
    const int nt = q0 / 64 + 2;

    auto issueK = [&](int kt) {
        const int k0 = kt * 64;
        const uint32_t kb = sb + FL2_KOF(kt & 1) * 2;
        #pragma unroll
        for (int p = 0; p < 4; p++) {
            const int ch = tid + p * 512;          // 0..2047
            const int part = ch >> 10;             // 0 hi, 1 lo
            const int c2 = ch & 1023;
            const int r = c2 >> 4, c8 = (c2 & 15) * 8;
            const __nv_bfloat16* src = (part ? Klo : Khi) + base + (size_t)(k0 + r) * HD + c8;
            cp16(kb + (uint32_t)(part * 8704 + r * 136 + c8) * 2, src);
        }
        cp_commit();
    };
    auto issueV = [&](int kt) {
        const int k0 = kt * 64;
        #pragma unroll
        for (int p = 0; p < 4; p++) {
            const int ch = tid + p * 512;
            const int part = ch >> 10;
            const int c2 = ch & 1023;
            const int d = c2 >> 3, s8 = (c2 & 7) * 8;
            const __nv_bfloat16* src = (part ? VTlo : VThi) + vbase + (size_t)d * S_ + k0 + s8;
            cp16(sb + (uint32_t)((part ? FL2_VLO : FL2_VHI) + d * 72 + s8) * 2, src);
        }
        cp_commit();
    };

    issueK(0);

    // Q tile -> smem (hi, lo)
    #pragma unroll
    for (int p = 0; p < 8; p++) {
        const int ch = tid + p * 512;              // 0..4095
        const int part = ch >> 11;
        const int c2 = ch & 2047;
        const int r = c2 >> 4, c8 = (c2 & 15) * 8;
        const __nv_bfloat16* src = (part ? Qlo : Qhi) + base + (size_t)(q0 + r) * HD + c8;
        *(uint4*)(sm + (part ? FL2_QLO : FL2_QHI) + r * 136 + c8) = *(const uint4*)src;
    }

    float oacc[16][4] = {};
    float m0 = -1e30f, m1 = -1e30f, l0 = 0.f, l1 = 0.f;
    const int r0 = q0 + wq * 16 + g;
    const int pme  = (wq * 2 + wc) * 16;          // my pmax slot base
    const int ppo  = (wq * 2 + (wc ^ 1)) * 16;    // partner slot base

    for (int kt = 0; kt < nt; kt++) {
        const int st = kt & 1;
        __syncthreads();                 // V buf + K[(kt+1)&1] buf free
        issueV(kt);
        if (kt + 1 < nt) { issueK(kt + 1); cp_wait<2>(); }
        else             { cp_wait<1>(); }
        __syncthreads();                 // K[kt] visible

        // ---- S = Q K^T over this warp's 32 cols (bf16x3) ----
        float sacc[4][4];
        #pragma unroll
        for (int j = 0; j < 4; j++)
            sacc[j][0] = sacc[j][1] = sacc[j][2] = sacc[j][3] = 0.f;
        const __nv_bfloat16* Ksm = sm + FL2_KOF(st);
        #pragma unroll
        for (int kk = 0; kk < 8; kk++) {
            const int ac = kk * 16 + 2 * tg;
            const int ar = (wq * 16 + g) * 136 + ac;
            uint32_t ah[4], al[4], bhh[4][2], bll[4][2];
            ah[0] = *(const uint32_t*)&sm[FL2_QHI + ar];
            ah[1] = *(const uint32_t*)&sm[FL2_QHI + ar + 8*136];
            ah[2] = *(const uint32_t*)&sm[FL2_QHI + ar + 8];
            ah[3] = *(const uint32_t*)&sm[FL2_QHI + ar + 8*136 + 8];
            #pragma unroll
            for (int j = 0; j < 4; j++) {
                const int br = (wc * 32 + j * 8 + g) * 136 + ac;
                bhh[j][0] = *(const uint32_t*)&Ksm[br];
                bhh[j][1] = *(const uint32_t*)&Ksm[br + 8];
            }
            #pragma unroll
            for (int j = 0; j < 4; j++) mma16816(sacc[j], ah, bhh[j]);
            #pragma unroll
            for (int j = 0; j < 4; j++) {
                const int br = 8704 + (wc * 32 + j * 8 + g) * 136 + ac;
                bll[j][0] = *(const uint32_t*)&Ksm[br];
                bll[j][1] = *(const uint32_t*)&Ksm[br + 8];
            }
            #pragma unroll
            for (int j = 0; j < 4; j++) mma16816(sacc[j], ah, bll[j]);
            al[0] = *(const uint32_t*)&sm[FL2_QLO + ar];
            al[1] = *(const uint32_t*)&sm[FL2_QLO + ar + 8*136];
            al[2] = *(const uint32_t*)&sm[FL2_QLO + ar + 8];
            al[3] = *(const uint32_t*)&sm[FL2_QLO + ar + 8*136 + 8];
            #pragma unroll
            for (int j = 0; j < 4; j++) mma16816(sacc[j], al, bhh[j]);
        }

        // ---- causal mask ----
        const int k0 = kt * 64;
        if (k0 + 63 > r0) {
            #pragma unroll
            for (int j = 0; j < 4; j++) {
                const int c = k0 + wc * 32 + j * 8 + 2 * tg;
                if (c     > r0)     sacc[j][0] = -1e30f;
                if (c + 1 > r0)     sacc[j][1] = -1e30f;
                if (c     > r0 + 8) sacc[j][2] = -1e30f;
                if (c + 1 > r0 + 8) sacc[j][3] = -1e30f;
            }
        }

        // ---- local row max over my 32 cols ----
        float rx0 = -1e30f, rx1 = -1e30f;
        #pragma unroll
        for (int j = 0; j < 4; j++) {
            rx0 = fmaxf(rx0, fmaxf(sacc[j][0], sacc[j][1]));
            rx1 = fmaxf(rx1, fmaxf(sacc[j][2], sacc[j][3]));
        }
        rx0 = fmaxf(rx0, __shfl_xor_sync(0xffffffffu, rx0, 1));
        rx0 = fmaxf(rx0, __shfl_xor_sync(0xffffffffu, rx0, 2));
        rx1 = fmaxf(rx1, __shfl_xor_sync(0xffffffffu, rx1, 1));
        rx1 = fmaxf(rx1, __shfl_xor_sync(0xffffffffu, rx1, 2));
        if (tg == 0) {
            smf[FL2_PMAXF + pme + g]     = rx0;
            smf[FL2_PMAXF + pme + g + 8] = rx1;
        }

        // wait V; sync also publishes pmax
        if (kt + 1 < nt) cp_wait<1>(); else cp_wait<0>();
        __syncthreads();

        // ---- combined max, P, partial l, rescale ----
        const float ox0 = smf[FL2_PMAXF + ppo + g];
        const float ox1 = smf[FL2_PMAXF + ppo + g + 8];
        const float mn0 = fmaxf(m0, fmaxf(rx0, ox0));
        const float mn1 = fmaxf(m1, fmaxf(rx1, ox1));
        const float c0 = __expf(m0 - mn0), c1 = __expf(m1 - mn1);

        uint32_t phA[4], phB[4], plA[4], plB[4];
        float sum0 = 0.f, sum1 = 0.f;
        #pragma unroll
        for (int j = 0; j < 4; j++) {
            float p00 = __expf(sacc[j][0] - mn0);
            float p01 = __expf(sacc[j][1] - mn0);
            float p10 = __expf(sacc[j][2] - mn1);
            float p11 = __expf(sacc[j][3] - mn1);
            sum0 += p00 + p01;  sum1 += p10 + p11;
            phA[j] = packbf(p00, p01);
            phB[j] = packbf(p10, p11);
            __nv_bfloat162 hA = *(__nv_bfloat162*)&phA[j];
            __nv_bfloat162 hB = *(__nv_bfloat162*)&phB[j];
            plA[j] = packbf(p00 - __bfloat162float(hA.x), p01 - __bfloat162float(hA.y));
            plB[j] = packbf(p10 - __bfloat162float(hB.x), p11 - __bfloat162float(hB.y));
        }
        sum0 += __shfl_xor_sync(0xffffffffu, sum0, 1);
        sum0 += __shfl_xor_sync(0xffffffffu, sum0, 2);
        sum1 += __shfl_xor_sync(0xffffffffu, sum1, 1);
        sum1 += __shfl_xor_sync(0xffffffffu, sum1, 2);
        l0 = l0 * c0 + sum0;  m0 = mn0;
        l1 = l1 * c1 + sum1;  m1 = mn1;
        #pragma unroll
        for (int jd = 0; jd < 16; jd++) {
            oacc[jd][0] *= c0; oacc[jd][1] *= c0;
            oacc[jd][2] *= c1; oacc[jd][3] *= c1;
        }

        // ---- O += P V over my 32 k-cols (bf16x3) ----
        #pragma unroll
        for (int kk2 = 0; kk2 < 2; kk2++) {
            uint32_t a_h[4] = { phA[2*kk2], phB[2*kk2], phA[2*kk2+1], phB[2*kk2+1] };
            uint32_t a_l[4] = { plA[2*kk2], plB[2*kk2], plA[2*kk2+1], plB[2*kk2+1] };
            const int ac = wc * 32 + kk2 * 16 + 2 * tg;
            #pragma unroll
            for (int jd = 0; jd < 16; jd++) {
                const int br = (jd * 8 + g) * 72 + ac;
                uint32_t bhv[2] = { *(const uint32_t*)&sm[FL2_VHI + br],
                                    *(const uint32_t*)&sm[FL2_VHI + br + 8] };
                mma16816(oacc[jd], a_h, bhv);
                mma16816(oacc[jd], a_l, bhv);
                uint32_t blv[2] = { *(const uint32_t*)&sm[FL2_VLO + br],
                                    *(const uint32_t*)&sm[FL2_VLO + br + 8] };
                mma16816(oacc[jd], a_h, blv);
            }
        }
    }

    // ---- combine partial O and l across warp pairs, write ctx ----
    __syncthreads();                 // everyone done; Q/K smem reusable
    if (wc == 1) {
        #pragma unroll
        for (int jd = 0; jd < 16; jd++) {
            const int d = jd * 8 + 2 * tg;
            *(float2*)&smf[(wq * 16 + g)     * 130 + d] = make_float2(oacc[jd][0], oacc[jd][1]);
            *(float2*)&smf[(wq * 16 + g + 8) * 130 + d] = make_float2(oacc[jd][2], oacc[jd][3]);
        }
        if (tg == 0) {
            smf[FL2_LSMF + wq * 16 + g]     = l0;
            smf[FL2_LSMF + wq * 16 + g + 8] = l1;
        }
    }
    __syncthreads();
    if (wc == 0) {
        const float lt0 = l0 + smf[FL2_LSMF + wq * 16 + g];
        const float lt1 = l1 + smf[FL2_LSMF + wq * 16 + g + 8];
        const float i0 = 1.f / lt0, i1 = 1.f / lt1;
        #pragma unroll
        for (int jd = 0; jd < 16; jd++) {
            const int d = jd * 8 + 2 * tg;
            float2 p0 = *(float2*)&smf[(wq * 16 + g)     * 130 + d];
            float2 p1 = *(float2*)&smf[(wq * 16 + g + 8) * 130 + d];
            const float o00 = (oacc[jd][0] + p0.x) * i0, o01 = (oacc[jd][1] + p0.y) * i0;
            const float o10 = (oacc[jd][2] + p1.x) * i1, o11 = (oacc[jd][3] + p1.y) * i1;
            const size_t idx0 = ((size_t)b * S_ + r0)     * H_ + head * HD + d;
            const size_t idx1 = ((size_t)b * S_ + r0 + 8) * H_ + head * HD + d;
            uint32_t h0 = packbf(o00, o01), h1 = packbf(o10, o11);
            __nv_bfloat162 hh0 = *(__nv_bfloat162*)&h0;
            __nv_bfloat162 hh1 = *(__nv_bfloat162*)&h1;
            uint32_t lo0 = packbf(o00 - __bfloat162float(hh0.x), o01 - __bfloat162float(hh0.y));
            uint32_t lo1 = packbf(o10 - __bfloat162float(hh1.x), o11 - __bfloat162float(hh1.y));
            *(uint32_t*)(Chi + idx0) = h0;  *(uint32_t*)(Clo + idx0) = lo0;
            *(uint32_t*)(Chi + idx1) = h1;  *(uint32_t*)(Clo + idx1) = lo1;
        }
    }
}

// ---------------------------------------------------------------------------
extern "C" void kernel_launch(void* const* d_in, const int* in_sizes, int n_in,
                              void* d_out, int out_size)
{
    const float* x  = (const float*)d_in[0];
    const float* wq = (const float*)d_in[1];
    const float* bq = (const float*)d_in[2];
    const float* wk = (const float*)d_in[3];
    const float* bk = (const float*)d_in[4];
    const float* wv = (const float*)d_in[5];
    const float* bv = (const float*)d_in[6];
    const float* wo = (const float*)d_in[7];
    const float* bo = (const float*)d_in[8];
    float* out = (float*)d_out;

    __nv_bfloat16 *xhi, *xlo, *whi, *wlo;
    __nv_bfloat16 *qhi, *qlo, *khi, *klo, *vthi, *vtlo, *chi, *clo;
    cudaGetSymbolAddress((void**)&xhi, g_xhi);
    cudaGetSymbolAddress((void**)&xlo, g_xlo);
    cudaGetSymbolAddress((void**)&whi, g_whi);
    cudaGetSymbolAddress((void**)&wlo, g_wlo);
    cudaGetSymbolAddress((void**)&qhi, g_qhi);
    cudaGetSymbolAddress((void**)&qlo, g_qlo);
    cudaGetSymbolAddress((void**)&khi, g_khi);
    cudaGetSymbolAddress((void**)&klo, g_klo);
    cudaGetSymbolAddress((void**)&vthi, g_vthi);
    cudaGetSymbolAddress((void**)&vtlo, g_vtlo);
    cudaGetSymbolAddress((void**)&chi, g_chi);
    cudaGetSymbolAddress((void**)&clo, g_clo);

    static bool attr_set = false;
    if (!attr_set) {
        cudaFuncSetAttribute(gemm_bf16x3<0>, cudaFuncAttributeMaxDynamicSharedMemorySize, GEMM_SMEM_BYTES);
        cudaFuncSetAttribute(gemm_bf16x3<1>, cudaFuncAttributeMaxDynamicSharedMemorySize, GEMM_SMEM_BYTES);
        cudaFuncSetAttribute(gemm_bf16x3<2>, cudaFuncAttributeMaxDynamicSharedMemorySize, GEMM_SMEM_BYTES);
        cudaFuncSetAttribute(flash_attn_v2, cudaFuncAttributeMaxDynamicSharedMemorySize, FL2_SMEM_BYTES);
        attr_set = true;
    }

    const size_t WN = (size_t)H_ * H_;
    const float qscale = 0.08838834764831845f;   // 1/sqrt(128)

    split_bf16<<<1024, 256>>>(x,  xhi, xlo, M_*H_/4);
    split_bf16<<<512,  256>>>(wq, whi + 0*WN, wlo + 0*WN, H_*H_/4);
    split_bf16<<<512,  256>>>(wk, whi + 1*WN, wlo + 1*WN, H_*H_/4);
    split_bf16<<<512,  256>>>(wv, whi + 2*WN, wlo + 2*WN, H_*H_/4);
    split_bf16<<<512,  256>>>(wo, whi + 3*WN, wlo + 3*WN, H_*H_/4);

    dim3 gg(H_/128, M_/128);
    gemm_bf16x3<0><<<gg, 256, GEMM_SMEM_BYTES>>>(xhi, xlo, whi + 0*WN, wlo + 0*WN, bq, qscale, nullptr, qhi, qlo);
    gemm_bf16x3<0><<<gg, 256, GEMM_SMEM_BYTES>>>(xhi, xlo, whi + 1*WN, wlo + 1*WN, bk, 1.f,    nullptr, khi, klo);
    gemm_bf16x3<2><<<gg, 256, GEMM_SMEM_BYTES>>>(xhi, xlo, whi + 2*WN, wlo + 2*WN, bv, 1.f,    nullptr, vthi, vtlo);

    dim3 gf(NQ, B_*NH);   // (16, 32)
    flash_attn_v2<<<gf, 512, FL2_SMEM_BYTES>>>(qhi, qlo, khi, klo, vthi, vtlo, chi, clo);

    gemm_bf16x3<1><<<gg, 256, GEMM_SMEM_BYTES>>>(chi, clo, whi + 3*WN, wlo + 3*WN, bo, 1.f, out, nullptr, nullptr);
}

// round 8
// speedup vs baseline: 1.0399x; 1.0399x over previous
#include <cuda_runtime.h>
#include <cuda_bf16.h>
#include <cstdint>

#define B_  2
#define S_  2048
#define H_  2048
#define NH  16
#define HD  128
#define M_  (B_*S_)
#define NQ  (S_/128)

// Single shared-memory symbol for the whole TU
extern __shared__ __align__(16) unsigned char sm_raw[];

// ---------------------------------------------------------------------------
// Scratch
// ---------------------------------------------------------------------------
__device__ __nv_bfloat16 g_xhi[(size_t)M_*H_];
__device__ __nv_bfloat16 g_xlo[(size_t)M_*H_];
__device__ __nv_bfloat16 g_whi[4][(size_t)H_*H_];
__device__ __nv_bfloat16 g_wlo[4][(size_t)H_*H_];
__device__ __nv_bfloat16 g_qhi[(size_t)M_*H_];   // [b,h,s,d], pre-scaled
__device__ __nv_bfloat16 g_qlo[(size_t)M_*H_];
__device__ __nv_bfloat16 g_khi[(size_t)M_*H_];   // [b,h,s,d]
__device__ __nv_bfloat16 g_klo[(size_t)M_*H_];
__device__ __nv_bfloat16 g_vhi[(size_t)M_*H_];   // [b,h,s,d] (NOT transposed)
__device__ __nv_bfloat16 g_vlo[(size_t)M_*H_];
__device__ __nv_bfloat16 g_chi[(size_t)M_*H_];   // [b,s,h]
__device__ __nv_bfloat16 g_clo[(size_t)M_*H_];

// ---------------------------------------------------------------------------
__device__ __forceinline__ void split1(float v, __nv_bfloat16& h, __nv_bfloat16& l) {
    h = __float2bfloat16(v);
    l = __float2bfloat16(v - __bfloat162float(h));
}

__global__ void split_bf16(const float* __restrict__ in,
                           __nv_bfloat16* __restrict__ hi,
                           __nv_bfloat16* __restrict__ lo, int n4)
{
    int i = blockIdx.x * blockDim.x + threadIdx.x;
    int stride = gridDim.x * blockDim.x;
    for (; i < n4; i += stride) {
        float4 v = ((const float4*)in)[i];
        __nv_bfloat16 h0,h1,h2,h3,l0,l1,l2,l3;
        split1(v.x,h0,l0); split1(v.y,h1,l1); split1(v.z,h2,l2); split1(v.w,h3,l3);
        ((__nv_bfloat162*)hi)[2*i+0] = __nv_bfloat162(h0,h1);
        ((__nv_bfloat162*)hi)[2*i+1] = __nv_bfloat162(h2,h3);
        ((__nv_bfloat162*)lo)[2*i+0] = __nv_bfloat162(l0,l1);
        ((__nv_bfloat162*)lo)[2*i+1] = __nv_bfloat162(l2,l3);
    }
}

// 4 weight matrices in one launch (blockIdx.y selects)
__global__ void split_bf16_w4(const float* __restrict__ w0, const float* __restrict__ w1,
                              const float* __restrict__ w2, const float* __restrict__ w3,
                              __nv_bfloat16* __restrict__ hi, __nv_bfloat16* __restrict__ lo,
                              int n4)
{
    const float* src[4] = {w0, w1, w2, w3};
    const float* in = src[blockIdx.y];
    __nv_bfloat16* hw = hi + (size_t)blockIdx.y * H_ * H_;
    __nv_bfloat16* lw = lo + (size_t)blockIdx.y * H_ * H_;
    int i = blockIdx.x * blockDim.x + threadIdx.x;
    int stride = gridDim.x * blockDim.x;
    for (; i < n4; i += stride) {
        float4 v = ((const float4*)in)[i];
        __nv_bfloat16 h0,h1,h2,h3,l0,l1,l2,l3;
        split1(v.x,h0,l0); split1(v.y,h1,l1); split1(v.z,h2,l2); split1(v.w,h3,l3);
        ((__nv_bfloat162*)hw)[2*i+0] = __nv_bfloat162(h0,h1);
        ((__nv_bfloat162*)hw)[2*i+1] = __nv_bfloat162(h2,h3);
        ((__nv_bfloat162*)lw)[2*i+0] = __nv_bfloat162(l0,l1);
        ((__nv_bfloat162*)lw)[2*i+1] = __nv_bfloat162(l2,l3);
    }
}

// ---------------------------------------------------------------------------
// PTX helpers
// ---------------------------------------------------------------------------
__device__ __forceinline__ uint32_t smem_u32(const void* p) {
    uint32_t a;
    asm("{ .reg .u64 t; cvta.to.shared.u64 t, %1; cvt.u32.u64 %0, t; }" : "=r"(a) : "l"(p));
    return a;
}
__device__ __forceinline__ void cp16(uint32_t s, const void* g) {
    asm volatile("cp.async.cg.shared.global [%0], [%1], 16;\n" :: "r"(s), "l"(g));
}
__device__ __forceinline__ void cp_commit() { asm volatile("cp.async.commit_group;\n"); }
template<int N> __device__ __forceinline__ void cp_wait() {
    asm volatile("cp.async.wait_group %0;\n" :: "n"(N));
}
__device__ __forceinline__ void mma16816(float* d, const uint32_t* a, const uint32_t* b) {
    asm volatile("mma.sync.aligned.m16n8k16.row.col.f32.bf16.bf16.f32 "
                 "{%0,%1,%2,%3}, {%4,%5,%6,%7}, {%8,%9}, {%0,%1,%2,%3};\n"
                 : "+f"(d[0]), "+f"(d[1]), "+f"(d[2]), "+f"(d[3])
                 : "r"(a[0]), "r"(a[1]), "r"(a[2]), "r"(a[3]), "r"(b[0]), "r"(b[1]));
}
__device__ __forceinline__ void ldsm4(uint32_t* r, uint32_t a) {
    asm volatile("ldmatrix.sync.aligned.m8n8.x4.shared.b16 {%0,%1,%2,%3}, [%4];"
                 : "=r"(r[0]), "=r"(r[1]), "=r"(r[2]), "=r"(r[3]) : "r"(a));
}
__device__ __forceinline__ void ldsm4t(uint32_t* r, uint32_t a) {
    asm volatile("ldmatrix.sync.aligned.m8n8.x4.trans.shared.b16 {%0,%1,%2,%3}, [%4];"
                 : "=r"(r[0]), "=r"(r[1]), "=r"(r[2]), "=r"(r[3]) : "r"(a));
}
__device__ __forceinline__ uint32_t packbf(float a, float b) {
    __nv_bfloat162 h(__float2bfloat16(a), __float2bfloat16(b));
    return *(uint32_t*)&h;
}

// ---------------------------------------------------------------------------
// bf16x3 GEMM (NT): C = A * W^T + bias.
// MODE 0: hi/lo pair out, scatter to [b,head,s,d] (* scale).  MODE 1: fp32 [M,N].
// ---------------------------------------------------------------------------
#define GSTRIDE 40
#define TILE_ELEMS (128*GSTRIDE)
#define STAGE_ELEMS (4*TILE_ELEMS)
#define GEMM_SMEM_BYTES (2*STAGE_ELEMS*2)

template<int MODE>
__global__ __launch_bounds__(256) void gemm_bf16x3(
    const __nv_bfloat16* __restrict__ Ahi, const __nv_bfloat16* __restrict__ Alo,
    const __nv_bfloat16* __restrict__ Whi, const __nv_bfloat16* __restrict__ Wlo,
    const float* __restrict__ bias, float scale,
    float* __restrict__ outf,
    __nv_bfloat16* __restrict__ outhi, __nv_bfloat16* __restrict__ outlo)
{
    __nv_bfloat16* sm = (__nv_bfloat16*)sm_raw;
    const int K = H_;
    const int tid  = threadIdx.x;
    const int lane = tid & 31, warp = tid >> 5;
    const int g = lane >> 2, tg = lane & 3;
    const int wm = (warp >> 2) * 64, wn = (warp & 3) * 32;
    const int bm = blockIdx.y * 128, bn = blockIdx.x * 128;

    const uint32_t sbase = smem_u32(sm);
    const int lrow0 = tid >> 2;
    const int lc8   = (tid & 3) * 8;
    const __nv_bfloat16* gA = Ahi + (size_t)(bm + lrow0) * K + lc8;
    const __nv_bfloat16* gAl= Alo + (size_t)(bm + lrow0) * K + lc8;
    const __nv_bfloat16* gW = Whi + (size_t)(bn + lrow0) * K + lc8;
    const __nv_bfloat16* gWl= Wlo + (size_t)(bn + lrow0) * K + lc8;
    const uint32_t soff0 = (uint32_t)(lrow0 * GSTRIDE + lc8) * 2;
    const uint32_t srowadd = 64 * GSTRIDE * 2;

    auto issue = [&](int kt, int buf) {
        const int k0 = kt * 32;
        uint32_t sb = sbase + buf * (STAGE_ELEMS * 2);
        #pragma unroll
        for (int t = 0; t < 2; t++) {
            uint32_t so = soff0 + t * srowadd;
            size_t go = (size_t)t * 64 * K + k0;
            cp16(sb + 0*TILE_ELEMS*2 + so, gA  + go);
            cp16(sb + 1*TILE_ELEMS*2 + so, gAl + go);
            cp16(sb + 2*TILE_ELEMS*2 + so, gW  + go);
            cp16(sb + 3*TILE_ELEMS*2 + so, gWl + go);
        }
        cp_commit();
    };

    float acc[4][4][4] = {};
    issue(0, 0);
    issue(1, 1);

    const int NT = K / 32;
    for (int kt = 0; kt < NT; kt++) {
        if (kt < NT - 1) cp_wait<1>(); else cp_wait<0>();
        __syncthreads();

        const __nv_bfloat16* As  = sm + (kt & 1) * STAGE_ELEMS;
        const __nv_bfloat16* Als = As + TILE_ELEMS;
        const __nv_bfloat16* Bs  = As + 2 * TILE_ELEMS;
        const __nv_bfloat16* Bls = As + 3 * TILE_ELEMS;

        #pragma unroll
        for (int kh = 0; kh < 32; kh += 16) {
            const int ac = kh + 2 * tg;
            uint32_t af[4][4], bh[4][2], bl[4][2];
            #pragma unroll
            for (int mi = 0; mi < 4; mi++) {
                const int r = (wm + mi * 16 + g) * GSTRIDE + ac;
                af[mi][0] = *(const uint32_t*)&As[r];
                af[mi][1] = *(const uint32_t*)&As[r + 8 * GSTRIDE];
                af[mi][2] = *(const uint32_t*)&As[r + 8];
                af[mi][3] = *(const uint32_t*)&As[r + 8 * GSTRIDE + 8];
            }
            #pragma unroll
            for (int ni = 0; ni < 4; ni++) {
                const int r = (wn + ni * 8 + g) * GSTRIDE + ac;
                bh[ni][0] = *(const uint32_t*)&Bs[r];
                bh[ni][1] = *(const uint32_t*)&Bs[r + 8];
            }
            #pragma unroll
            for (int mi = 0; mi < 4; mi++)
                #pragma unroll
                for (int ni = 0; ni < 4; ni++)
                    mma16816(acc[mi][ni], af[mi], bh[ni]);
            #pragma unroll
            for (int ni = 0; ni < 4; ni++) {
                const int r = (wn + ni * 8 + g) * GSTRIDE + ac;
                bl[ni][0] = *(const uint32_t*)&Bls[r];
                bl[ni][1] = *(const uint32_t*)&Bls[r + 8];
            }
            #pragma unroll
            for (int mi = 0; mi < 4; mi++)
                #pragma unroll
                for (int ni = 0; ni < 4; ni++)
                    mma16816(acc[mi][ni], af[mi], bl[ni]);
            #pragma unroll
            for (int mi = 0; mi < 4; mi++) {
                const int r = (wm + mi * 16 + g) * GSTRIDE + ac;
                af[mi][0] = *(const uint32_t*)&Als[r];
                af[mi][1] = *(const uint32_t*)&Als[r + 8 * GSTRIDE];
                af[mi][2] = *(const uint32_t*)&Als[r + 8];
                af[mi][3] = *(const uint32_t*)&Als[r + 8 * GSTRIDE + 8];
            }
            #pragma unroll
            for (int mi = 0; mi < 4; mi++)
                #pragma unroll
                for (int ni = 0; ni < 4; ni++)
                    mma16816(acc[mi][ni], af[mi], bh[ni]);
        }
        __syncthreads();
        if (kt + 2 < NT) issue(kt + 2, kt & 1);
    }

    // epilogue
    #pragma unroll
    for (int ni = 0; ni < 4; ni++) {
        const int n0 = bn + wn + ni * 8 + 2 * tg;
        const float b0 = bias[n0], b1 = bias[n0 + 1];
        #pragma unroll
        for (int mi = 0; mi < 4; mi++) {
            #pragma unroll
            for (int h = 0; h < 2; h++) {
                const int row = bm + wm + mi * 16 + g + h * 8;
                float vx = acc[mi][ni][2*h+0] + b0;
                float vy = acc[mi][ni][2*h+1] + b1;
                if (MODE == 1) {
                    *(float2*)(outf + (size_t)row * H_ + n0) = make_float2(vx, vy);
                } else {
                    vx *= scale; vy *= scale;
                    __nv_bfloat16 hx, hy, lx, ly;
                    split1(vx, hx, lx); split1(vy, hy, ly);
                    const int b  = row >> 11;
                    const int s  = row & 2047;
                    const int hd = n0 >> 7;
                    const int dd = n0 & 127;
                    size_t idx = ((size_t)(b * NH + hd) * S_ + s) * HD + dd;
                    *(__nv_bfloat162*)(outhi + idx) = __nv_bfloat162(hx, hy);
                    *(__nv_bfloat162*)(outlo + idx) = __nv_bfloat162(lx, ly);
                }
            }
        }
    }
}

// ---------------------------------------------------------------------------
// Flash attention v3b: 256 threads (8 warps), BR=128, BC=64.
// Warp w owns rows q0+16w..+15. Q frags in registers (loaded once from gmem).
// K/V double-buffered in smem [64][136] hi+lo each; K b-frags via ldmatrix.x4,
// V b-frags via ldmatrix.x4.trans (V stored [s][d] like K, no transpose pass).
// P kept as hi/lo bf16 pair (3-term PV) — required for rel_err < 1e-3.
// smem layout (bf16 elems): K st: st*17408 (hi 0, lo +8704)
//                           V st: 34816 + st*17408 (hi 0, lo +8704)
// ---------------------------------------------------------------------------
#define FV_K(st) ((st)*17408)
#define FV_V(st) (34816 + (st)*17408)
#define FV_SMEM_BYTES (69632*2)

__global__ __launch_bounds__(256) void flash_attn_v3(
    const __nv_bfloat16* __restrict__ Qhi, const __nv_bfloat16* __restrict__ Qlo,
    const __nv_bfloat16* __restrict__ Khi, const __nv_bfloat16* __restrict__ Klo,
    const __nv_bfloat16* __restrict__ Vhi, const __nv_bfloat16* __restrict__ Vlo,
    __nv_bfloat16* __restrict__ Chi, __nv_bfloat16* __restrict__ Clo)
{
    __nv_bfloat16* sm = (__nv_bfloat16*)sm_raw;
    const int tid = threadIdx.x, lane = tid & 31, w = tid >> 5;
    const int g = lane >> 2, tg = lane & 3;
    const int bh = blockIdx.y, b = bh >> 4, head = bh & 15;
    const int q0 = (NQ - 1 - (int)blockIdx.x) * 128;   // heavy blocks first
    const size_t base = (size_t)bh * S_ * HD;
    const uint32_t sb = smem_u32(sm);
    const int nt = q0 / 64 + 2;

    // ldmatrix lane address components
    const int sub   = lane & 7;
    const int halfb = (lane >> 3) & 1;
    const int grpb  = lane >> 4;

    auto issueKV = [&](int kt, int st) {
        const int k0 = kt * 64;
        const uint32_t kb = sb + FV_K(st) * 2;
        const uint32_t vb = sb + FV_V(st) * 2;
        #pragma unroll
        for (int p = 0; p < 4; p++) {
            const int ch = tid + p * 256;              // 0..1023
            const int r = ch >> 4, c8 = (ch & 15) * 8;
            const uint32_t off = (uint32_t)(r * 136 + c8) * 2;
            const size_t go = base + (size_t)(k0 + r) * HD + c8;
            cp16(kb + off,          Khi + go);
            cp16(kb + 17408 + off,  Klo + go);   // 8704*2 bytes
            cp16(vb + off,          Vhi + go);
            cp16(vb + 17408 + off,  Vlo + go);
        }
        cp_commit();
    };

    issueKV(0, 0);

    // ---- Q fragments -> registers (once) ----
    uint32_t qh[8][4], ql[8][4];
    {
        const size_t r0g = base + (size_t)(q0 + w * 16 + g) * HD;
        #pragma unroll
        for (int kk = 0; kk < 8; kk++) {
            const int c = kk * 16 + 2 * tg;
            qh[kk][0] = *(const uint32_t*)(Qhi + r0g + c);
            qh[kk][1] = *(const uint32_t*)(Qhi + r0g + 8 * HD + c);
            qh[kk][2] = *(const uint32_t*)(Qhi + r0g + c + 8);
            qh[kk][3] = *(const uint32_t*)(Qhi + r0g + 8 * HD + c + 8);
            ql[kk][0] = *(const uint32_t*)(Qlo + r0g + c);
            ql[kk][1] = *(const uint32_t*)(Qlo + r0g + 8 * HD + c);
            ql[kk][2] = *(const uint32_t*)(Qlo + r0g + c + 8);
            ql[kk][3] = *(const uint32_t*)(Qlo + r0g + 8 * HD + c + 8);
        }
    }

    float oacc[16][4] = {};
    float m0 = -1e30f, m1 = -1e30f, l0 = 0.f, l1 = 0.f;
    const int r0 = q0 + w * 16 + g;

    const uint32_t kfragoff = (uint32_t)((8 * grpb + sub) * 136 + halfb * 8) * 2;
    const uint32_t vfragoff = (uint32_t)((8 * halfb + sub) * 136 + 8 * grpb) * 2;

    for (int kt = 0; kt < nt; kt++) {
        const int st = kt & 1;
        __syncthreads();
        if (kt + 1 < nt) { issueKV(kt + 1, st ^ 1); cp_wait<1>(); }
        else             { cp_wait<0>(); }
        __syncthreads();

        // ---- S = Q K^T (bf16x3; Q in regs, K via ldmatrix) ----
        float sacc[8][4];
        #pragma unroll
        for (int j = 0; j < 8; j++)
            sacc[j][0] = sacc[j][1] = sacc[j][2] = sacc[j][3] = 0.f;
        const uint32_t kbase = sb + FV_K(st) * 2 + kfragoff;
        #pragma unroll
        for (int kk = 0; kk < 8; kk++) {
            #pragma unroll
            for (int jp = 0; jp < 4; jp++) {
                uint32_t bh4[4], bl4[4];
                const uint32_t ka = kbase + (uint32_t)(16 * jp * 136 + kk * 16) * 2;
                ldsm4(bh4, ka);
                ldsm4(bl4, ka + 17408);
                mma16816(sacc[2*jp],   qh[kk], bh4);
                mma16816(sacc[2*jp+1], qh[kk], bh4 + 2);
                mma16816(sacc[2*jp],   qh[kk], bl4);
                mma16816(sacc[2*jp+1], qh[kk], bl4 + 2);
                mma16816(sacc[2*jp],   ql[kk], bh4);
                mma16816(sacc[2*jp+1], ql[kk], bh4 + 2);
            }
        }

        // ---- causal mask ----
        const int k0 = kt * 64;
        if (k0 + 63 > r0) {
            #pragma unroll
            for (int j = 0; j < 8; j++) {
                const int c = k0 + j * 8 + 2 * tg;
                if (c     > r0)     sacc[j][0] = -1e30f;
                if (c + 1 > r0)     sacc[j][1] = -1e30f;
                if (c     > r0 + 8) sacc[j][2] = -1e30f;
                if (c + 1 > r0 + 8) sacc[j][3] = -1e30f;
            }
        }

        // ---- online softmax (P hi/lo bf16) ----
        float rx0 = -1e30f, rx1 = -1e30f;
        #pragma unroll
        for (int j = 0; j < 8; j++) {
            rx0 = fmaxf(rx0, fmaxf(sacc[j][0], sacc[j][1]));
            rx1 = fmaxf(rx1, fmaxf(sacc[j][2], sacc[j][3]));
        }
        rx0 = fmaxf(rx0, __shfl_xor_sync(0xffffffffu, rx0, 1));
        rx0 = fmaxf(rx0, __shfl_xor_sync(0xffffffffu, rx0, 2));
        rx1 = fmaxf(rx1, __shfl_xor_sync(0xffffffffu, rx1, 1));
        rx1 = fmaxf(rx1, __shfl_xor_sync(0xffffffffu, rx1, 2));
        const float mn0 = fmaxf(m0, rx0), mn1 = fmaxf(m1, rx1);
        const float c0 = __expf(m0 - mn0), c1 = __expf(m1 - mn1);

        uint32_t ph0[8], ph1[8], pl0[8], pl1[8];
        float sum0 = 0.f, sum1 = 0.f;
        #pragma unroll
        for (int j = 0; j < 8; j++) {
            float p00 = __expf(sacc[j][0] - mn0);
            float p01 = __expf(sacc[j][1] - mn0);
            float p10 = __expf(sacc[j][2] - mn1);
            float p11 = __expf(sacc[j][3] - mn1);
            sum0 += p00 + p01;  sum1 += p10 + p11;
            ph0[j] = packbf(p00, p01);
            ph1[j] = packbf(p10, p11);
            __nv_bfloat162 hA = *(__nv_bfloat162*)&ph0[j];
            __nv_bfloat162 hB = *(__nv_bfloat162*)&ph1[j];
            pl0[j] = packbf(p00 - __bfloat162float(hA.x), p01 - __bfloat162float(hA.y));
            pl1[j] = packbf(p10 - __bfloat162float(hB.x), p11 - __bfloat162float(hB.y));
        }
        sum0 += __shfl_xor_sync(0xffffffffu, sum0, 1);
        sum0 += __shfl_xor_sync(0xffffffffu, sum0, 2);
        sum1 += __shfl_xor_sync(0xffffffffu, sum1, 1);
        sum1 += __shfl_xor_sync(0xffffffffu, sum1, 2);
        l0 = l0 * c0 + sum0;  m0 = mn0;
        l1 = l1 * c1 + sum1;  m1 = mn1;
        #pragma unroll
        for (int jd = 0; jd < 16; jd++) {
            oacc[jd][0] *= c0; oacc[jd][1] *= c0;
            oacc[jd][2] *= c1; oacc[jd][3] *= c1;
        }

        // ---- O += P V (3-term bf16x3; P in regs, V via ldmatrix.trans) ----
        const uint32_t vbase = sb + FV_V(st) * 2 + vfragoff;
        #pragma unroll
        for (int kk2 = 0; kk2 < 4; kk2++) {
            uint32_t a_h[4] = { ph0[2*kk2], ph1[2*kk2], ph0[2*kk2+1], ph1[2*kk2+1] };
            uint32_t a_l[4] = { pl0[2*kk2], pl1[2*kk2], pl0[2*kk2+1], pl1[2*kk2+1] };
            #pragma unroll
            for (int jdp = 0; jdp < 8; jdp++) {
                uint32_t vh4[4], vl4[4];
                const uint32_t va = vbase + (uint32_t)(16 * kk2 * 136 + 16 * jdp) * 2;
                ldsm4t(vh4, va);
                ldsm4t(vl4, va + 17408);
                mma16816(oacc[2*jdp],   a_h, vh4);
                mma16816(oacc[2*jdp+1], a_h, vh4 + 2);
                mma16816(oacc[2*jdp],   a_l, vh4);
                mma16816(oacc[2*jdp+1], a_l, vh4 + 2);
                mma16816(oacc[2*jdp],   a_h, vl4);
                mma16816(oacc[2*jdp+1], a_h, vl4 + 2);
            }
        }
    }

    // ---- epilogue: normalize, hi/lo bf16, write ctx [b,s,h] ----
    const float i0 = 1.f / l0, i1 = 1.f / l1;
    #pragma unroll
    for (int jd = 0; jd < 16; jd++) {
        const int d = jd * 8 + 2 * tg;
        const float o00 = oacc[jd][0] * i0, o01 = oacc[jd][1] * i0;
        const float o10 = oacc[jd][2] * i1, o11 = oacc[jd][3] * i1;
        const size_t idx0 = ((size_t)b * S_ + r0)     * H_ + head * HD + d;
        const size_t idx1 = ((size_t)b * S_ + r0 + 8) * H_ + head * HD + d;
        __nv_bfloat16 hx, hy, lx, ly;
        split1(o00, hx, lx); split1(o01, hy, ly);
        *(__nv_bfloat162*)(Chi + idx0) = __nv_bfloat162(hx, hy);
        *(__nv_bfloat162*)(Clo + idx0) = __nv_bfloat162(lx, ly);
        split1(o10, hx, lx); split1(o11, hy, ly);
        *(__nv_bfloat162*)(Chi + idx1) = __nv_bfloat162(hx, hy);
        *(__nv_bfloat162*)(Clo + idx1) = __nv_bfloat162(lx, ly);
    }
}

// ---------------------------------------------------------------------------
extern "C" void kernel_launch(void* const* d_in, const int* in_sizes, int n_in,
                              void* d_out, int out_size)
{
    const float* x  = (const float*)d_in[0];
    const float* wq = (const float*)d_in[1];
    const float* bq = (const float*)d_in[2];
    const float* wk = (const float*)d_in[3];
    const float* bk = (const float*)d_in[4];
    const float* wv = (const float*)d_in[5];
    const float* bv = (const float*)d_in[6];
    const float* wo = (const float*)d_in[7];
    const float* bo = (const float*)d_in[8];
    float* out = (float*)d_out;

    __nv_bfloat16 *xhi, *xlo, *whi, *wlo;
    __nv_bfloat16 *qhi, *qlo, *khi, *klo, *vhi, *vlo, *chi, *clo;
    cudaGetSymbolAddress((void**)&xhi, g_xhi);
    cudaGetSymbolAddress((void**)&xlo, g_xlo);
    cudaGetSymbolAddress((void**)&whi, g_whi);
    cudaGetSymbolAddress((void**)&wlo, g_wlo);
    cudaGetSymbolAddress((void**)&qhi, g_qhi);
    cudaGetSymbolAddress((void**)&qlo, g_qlo);
    cudaGetSymbolAddress((void**)&khi, g_khi);
    cudaGetSymbolAddress((void**)&klo, g_klo);
    cudaGetSymbolAddress((void**)&vhi, g_vhi);
    cudaGetSymbolAddress((void**)&vlo, g_vlo);
    cudaGetSymbolAddress((void**)&chi, g_chi);
    cudaGetSymbolAddress((void**)&clo, g_clo);

    static bool attr_set = false;
    if (!attr_set) {
        cudaFuncSetAttribute(gemm_bf16x3<0>, cudaFuncAttributeMaxDynamicSharedMemorySize, GEMM_SMEM_BYTES);
        cudaFuncSetAttribute(gemm_bf16x3<1>, cudaFuncAttributeMaxDynamicSharedMemorySize, GEMM_SMEM_BYTES);
        cudaFuncSetAttribute(flash_attn_v3, cudaFuncAttributeMaxDynamicSharedMemorySize, FV_SMEM_BYTES);
        attr_set = true;
    }

    const size_t WN = (size_t)H_ * H_;
    const float qscale = 0.08838834764831845f;   // 1/sqrt(128)

    split_bf16<<<1024, 256>>>(x, xhi, xlo, M_*H_/4);
    split_bf16_w4<<<dim3(256, 4), 256>>>(wq, wk, wv, wo, whi, wlo, H_*H_/4);

    dim3 gg(H_/128, M_/128);
    gemm_bf16x3<0><<<gg, 256, GEMM_SMEM_BYTES>>>(xhi, xlo, whi + 0*WN, wlo + 0*WN, bq, qscale, nullptr, qhi, qlo);
    gemm_bf16x3<0><<<gg, 256, GEMM_SMEM_BYTES>>>(xhi, xlo, whi + 1*WN, wlo + 1*WN, bk, 1.f,    nullptr, khi, klo);
    gemm_bf16x3<0><<<gg, 256, GEMM_SMEM_BYTES>>>(xhi, xlo, whi + 2*WN, wlo + 2*WN, bv, 1.f,    nullptr, vhi, vlo);

    dim3 gf(NQ, B_*NH);   // (16, 32)
    flash_attn_v3<<<gf, 256, FV_SMEM_BYTES>>>(qhi, qlo, khi, klo, vhi, vlo, chi, clo);

    gemm_bf16x3<1><<<gg, 256, GEMM_SMEM_BYTES>>>(chi, clo, whi + 3*WN, wlo + 3*WN, bo, 1.f, out, nullptr, nullptr);
}

// round 10
// speedup vs baseline: 1.2032x; 1.1570x over previous
#include <cuda_runtime.h>
#include <cuda_bf16.h>
#include <cstdint>

#define B_  2
#define S_  2048
#define H_  2048
#define NH  16
#define HD  128
#define M_  (B_*S_)
#define NQ  (S_/128)

// Single shared-memory symbol for the whole TU
extern __shared__ __align__(16) unsigned char sm_raw[];

// ---------------------------------------------------------------------------
// Scratch
// ---------------------------------------------------------------------------
__device__ __nv_bfloat16 g_xhi[(size_t)M_*H_];
__device__ __nv_bfloat16 g_xlo[(size_t)M_*H_];
__device__ __nv_bfloat16 g_whi[4][(size_t)H_*H_];
__device__ __nv_bfloat16 g_wlo[4][(size_t)H_*H_];
__device__ __nv_bfloat16 g_qhi[(size_t)M_*H_];   // [b,h,s,d], pre-scaled
__device__ __nv_bfloat16 g_qlo[(size_t)M_*H_];
__device__ __nv_bfloat16 g_khi[(size_t)M_*H_];   // [b,h,s,d]
__device__ __nv_bfloat16 g_klo[(size_t)M_*H_];
__device__ __nv_bfloat16 g_vhi[(size_t)M_*H_];   // [b,h,s,d]
__device__ __nv_bfloat16 g_vlo[(size_t)M_*H_];
__device__ __nv_bfloat16 g_chi[(size_t)M_*H_];   // [b,s,h]
__device__ __nv_bfloat16 g_clo[(size_t)M_*H_];

// ---------------------------------------------------------------------------
__device__ __forceinline__ void split1(float v, __nv_bfloat16& h, __nv_bfloat16& l) {
    h = __float2bfloat16(v);
    l = __float2bfloat16(v - __bfloat162float(h));
}

__global__ void split_bf16(const float* __restrict__ in,
                           __nv_bfloat16* __restrict__ hi,
                           __nv_bfloat16* __restrict__ lo, int n4)
{
    int i = blockIdx.x * blockDim.x + threadIdx.x;
    int stride = gridDim.x * blockDim.x;
    for (; i < n4; i += stride) {
        float4 v = ((const float4*)in)[i];
        __nv_bfloat16 h0,h1,h2,h3,l0,l1,l2,l3;
        split1(v.x,h0,l0); split1(v.y,h1,l1); split1(v.z,h2,l2); split1(v.w,h3,l3);
        ((__nv_bfloat162*)hi)[2*i+0] = __nv_bfloat162(h0,h1);
        ((__nv_bfloat162*)hi)[2*i+1] = __nv_bfloat162(h2,h3);
        ((__nv_bfloat162*)lo)[2*i+0] = __nv_bfloat162(l0,l1);
        ((__nv_bfloat162*)lo)[2*i+1] = __nv_bfloat162(l2,l3);
    }
}

__global__ void split_bf16_w4(const float* __restrict__ w0, const float* __restrict__ w1,
                              const float* __restrict__ w2, const float* __restrict__ w3,
                              __nv_bfloat16* __restrict__ hi, __nv_bfloat16* __restrict__ lo,
                              int n4)
{
    const float* src[4] = {w0, w1, w2, w3};
    const float* in = src[blockIdx.y];
    __nv_bfloat16* hw = hi + (size_t)blockIdx.y * H_ * H_;
    __nv_bfloat16* lw = lo + (size_t)blockIdx.y * H_ * H_;
    int i = blockIdx.x * blockDim.x + threadIdx.x;
    int stride = gridDim.x * blockDim.x;
    for (; i < n4; i += stride) {
        float4 v = ((const float4*)in)[i];
        __nv_bfloat16 h0,h1,h2,h3,l0,l1,l2,l3;
        split1(v.x,h0,l0); split1(v.y,h1,l1); split1(v.z,h2,l2); split1(v.w,h3,l3);
        ((__nv_bfloat162*)hw)[2*i+0] = __nv_bfloat162(h0,h1);
        ((__nv_bfloat162*)hw)[2*i+1] = __nv_bfloat162(h2,h3);
        ((__nv_bfloat162*)lw)[2*i+0] = __nv_bfloat162(l0,l1);
        ((__nv_bfloat162*)lw)[2*i+1] = __nv_bfloat162(l2,l3);
    }
}

// ---------------------------------------------------------------------------
// PTX helpers
// ---------------------------------------------------------------------------
__device__ __forceinline__ uint32_t smem_u32(const void* p) {
    uint32_t a;
    asm("{ .reg .u64 t; cvta.to.shared.u64 t, %1; cvt.u32.u64 %0, t; }" : "=r"(a) : "l"(p));
    return a;
}
__device__ __forceinline__ void cp16(uint32_t s, const void* g) {
    asm volatile("cp.async.cg.shared.global [%0], [%1], 16;\n" :: "r"(s), "l"(g));
}
__device__ __forceinline__ void cp_commit() { asm volatile("cp.async.commit_group;\n"); }
template<int N> __device__ __forceinline__ void cp_wait() {
    asm volatile("cp.async.wait_group %0;\n" :: "n"(N));
}
__device__ __forceinline__ void mma16816(float* d, const uint32_t* a, const uint32_t* b) {
    asm volatile("mma.sync.aligned.m16n8k16.row.col.f32.bf16.bf16.f32 "
                 "{%0,%1,%2,%3}, {%4,%5,%6,%7}, {%8,%9}, {%0,%1,%2,%3};\n"
                 : "+f"(d[0]), "+f"(d[1]), "+f"(d[2]), "+f"(d[3])
                 : "r"(a[0]), "r"(a[1]), "r"(a[2]), "r"(a[3]), "r"(b[0]), "r"(b[1]));
}
__device__ __forceinline__ void ldsm4(uint32_t* r, uint32_t a) {
    asm volatile("ldmatrix.sync.aligned.m8n8.x4.shared.b16 {%0,%1,%2,%3}, [%4];"
                 : "=r"(r[0]), "=r"(r[1]), "=r"(r[2]), "=r"(r[3]) : "r"(a));
}
__device__ __forceinline__ void ldsm4t(uint32_t* r, uint32_t a) {
    asm volatile("ldmatrix.sync.aligned.m8n8.x4.trans.shared.b16 {%0,%1,%2,%3}, [%4];"
                 : "=r"(r[0]), "=r"(r[1]), "=r"(r[2]), "=r"(r[3]) : "r"(a));
}
__device__ __forceinline__ uint32_t packbf(float a, float b) {
    __nv_bfloat162 h(__float2bfloat16(a), __float2bfloat16(b));
    return *(uint32_t*)&h;
}

// ---------------------------------------------------------------------------
// bf16x3 GEMM (NT): C = A * W^T + bias, mma.sync + ldmatrix fragment loads.
// BM=BN=128, BK=32, 256 threads (8 warps 2x4), warp tile 64x32.
// MODE 0: QKV fused — blockIdx.z selects {Q,K,V} weight/bias/output;
//         hi/lo bf16 out scattered to [b,head,s,d] (*scale for Q).
// MODE 1: single GEMM, fp32 out [M,N].
// ---------------------------------------------------------------------------
#define GSTRIDE 40
#define TILE_ELEMS (128*GSTRIDE)
#define STAGE_ELEMS (4*TILE_ELEMS)
#define GEMM_SMEM_BYTES (2*STAGE_ELEMS*2)

template<int MODE>
__global__ __launch_bounds__(256) void gemm_bf16x3(
    const __nv_bfloat16* __restrict__ Ahi, const __nv_bfloat16* __restrict__ Alo,
    const __nv_bfloat16* __restrict__ Wh_base, const __nv_bfloat16* __restrict__ Wl_base,
    const float* __restrict__ bias0, const float* __restrict__ bias1,
    const float* __restrict__ bias2, float scale0,
    float* __restrict__ outf,
    __nv_bfloat16* __restrict__ oh0, __nv_bfloat16* __restrict__ ol0,
    __nv_bfloat16* __restrict__ oh1, __nv_bfloat16* __restrict__ ol1,
    __nv_bfloat16* __restrict__ oh2, __nv_bfloat16* __restrict__ ol2)
{
    __nv_bfloat16* sm = (__nv_bfloat16*)sm_raw;
    const int K = H_;
    const int tid  = threadIdx.x;
    const int lane = tid & 31, warp = tid >> 5;
    const int g = lane >> 2, tg = lane & 3;
    const int wm = (warp >> 2) * 64, wn = (warp & 3) * 32;
    const int bm = blockIdx.y * 128, bn = blockIdx.x * 128;
    const int z = (MODE == 0) ? blockIdx.z : 0;

    const __nv_bfloat16* Whi = Wh_base + (size_t)z * H_ * H_;
    const __nv_bfloat16* Wlo = Wl_base + (size_t)z * H_ * H_;
    const float* bias = (z == 0) ? bias0 : (z == 1) ? bias1 : bias2;
    const float scale = (MODE == 0 && z == 0) ? scale0 : 1.f;
    __nv_bfloat16* outhi = (z == 0) ? oh0 : (z == 1) ? oh1 : oh2;
    __nv_bfloat16* outlo = (z == 0) ? ol0 : (z == 1) ? ol1 : ol2;

    const uint32_t sbase = smem_u32(sm);
    const int lrow0 = tid >> 2;
    const int lc8   = (tid & 3) * 8;
    const __nv_bfloat16* gA = Ahi + (size_t)(bm + lrow0) * K + lc8;
    const __nv_bfloat16* gAl= Alo + (size_t)(bm + lrow0) * K + lc8;
    const __nv_bfloat16* gW = Whi + (size_t)(bn + lrow0) * K + lc8;
    const __nv_bfloat16* gWl= Wlo + (size_t)(bn + lrow0) * K + lc8;
    const uint32_t soff0 = (uint32_t)(lrow0 * GSTRIDE + lc8) * 2;
    const uint32_t srowadd = 64 * GSTRIDE * 2;

    auto issue = [&](int kt, int buf) {
        const int k0 = kt * 32;
        uint32_t sb = sbase + buf * (STAGE_ELEMS * 2);
        #pragma unroll
        for (int t = 0; t < 2; t++) {
            uint32_t so = soff0 + t * srowadd;
            size_t go = (size_t)t * 64 * K + k0;
            cp16(sb + 0*TILE_ELEMS*2 + so, gA  + go);
            cp16(sb + 1*TILE_ELEMS*2 + so, gAl + go);
            cp16(sb + 2*TILE_ELEMS*2 + so, gW  + go);
            cp16(sb + 3*TILE_ELEMS*2 + so, gWl + go);
        }
        cp_commit();
    };

    float acc[4][4][4] = {};
    issue(0, 0);
    issue(1, 1);

    // ldmatrix per-lane offsets (bytes), relative to tile base
    const int sub = lane & 7;
    // A frags: mat0 rows+0/k+0, mat1 rows+8/k+0, mat2 rows+0/k+8, mat3 rows+8/k+8
    const uint32_t a_off = ((uint32_t)((8 * ((lane >> 3) & 1) + sub) * GSTRIDE
                                       + (lane >> 4) * 8)) * 2;
    // B frags: mat0 n+0/k+0, mat1 n+0/k+8, mat2 n+8/k+0, mat3 n+8/k+8
    const uint32_t b_off = ((uint32_t)((8 * (lane >> 4) + sub) * GSTRIDE
                                       + ((lane >> 3) & 1) * 8)) * 2;

    const int NT = K / 32;
    for (int kt = 0; kt < NT; kt++) {
        if (kt < NT - 1) cp_wait<1>(); else cp_wait<0>();
        __syncthreads();

        const uint32_t stb = sbase + (kt & 1) * (STAGE_ELEMS * 2);

        #pragma unroll
        for (int kh = 0; kh < 32; kh += 16) {
            const uint32_t Aaddr = stb + a_off + (uint32_t)(wm * GSTRIDE + kh) * 2;
            const uint32_t Baddr = stb + 2*TILE_ELEMS*2 + b_off
                                 + (uint32_t)(wn * GSTRIDE + kh) * 2;
            uint32_t afh[4][4], afl[4][4], bhh[2][4], bll[2][4];
            #pragma unroll
            for (int mi = 0; mi < 4; mi++)
                ldsm4(afh[mi], Aaddr + (uint32_t)(mi * 16 * GSTRIDE) * 2);
            ldsm4(bhh[0], Baddr);
            ldsm4(bhh[1], Baddr + (uint32_t)(16 * GSTRIDE) * 2);
            // hi*hi
            #pragma unroll
            for (int mi = 0; mi < 4; mi++)
                #pragma unroll
                for (int ni = 0; ni < 4; ni++)
                    mma16816(acc[mi][ni], afh[mi], bhh[ni >> 1] + (ni & 1) * 2);
            // hi*lo (B lo)
            ldsm4(bll[0], Baddr + TILE_ELEMS*2);
            ldsm4(bll[1], Baddr + TILE_ELEMS*2 + (uint32_t)(16 * GSTRIDE) * 2);
            #pragma unroll
            for (int mi = 0; mi < 4; mi++)
                #pragma unroll
                for (int ni = 0; ni < 4; ni++)
                    mma16816(acc[mi][ni], afh[mi], bll[ni >> 1] + (ni & 1) * 2);
            // lo*hi (A lo)
            #pragma unroll
            for (int mi = 0; mi < 4; mi++)
                ldsm4(afl[mi], Aaddr + TILE_ELEMS*2 + (uint32_t)(mi * 16 * GSTRIDE) * 2);
            #pragma unroll
            for (int mi = 0; mi < 4; mi++)
                #pragma unroll
                for (int ni = 0; ni < 4; ni++)
                    mma16816(acc[mi][ni], afl[mi], bhh[ni >> 1] + (ni & 1) * 2);
        }
        __syncthreads();
        if (kt + 2 < NT) issue(kt + 2, kt & 1);
    }

    // epilogue
    #pragma unroll
    for (int ni = 0; ni < 4; ni++) {
        const int n0 = bn + wn + ni * 8 + 2 * tg;
        const float b0 = bias[n0], b1 = bias[n0 + 1];
        #pragma unroll
        for (int mi = 0; mi < 4; mi++) {
            #pragma unroll
            for (int h = 0; h < 2; h++) {
                const int row = bm + wm + mi * 16 + g + h * 8;
                float vx = acc[mi][ni][2*h+0] + b0;
                float vy = acc[mi][ni][2*h+1] + b1;
                if (MODE == 1) {
                    *(float2*)(outf + (size_t)row * H_ + n0) = make_float2(vx, vy);
                } else {
                    vx *= scale; vy *= scale;
                    __nv_bfloat16 hx, hy, lx, ly;
                    split1(vx, hx, lx); split1(vy, hy, ly);
                    const int b  = row >> 11;
                    const int s  = row & 2047;
                    const int hd = n0 >> 7;
                    const int dd = n0 & 127;
                    size_t idx = ((size_t)(b * NH + hd) * S_ + s) * HD + dd;
                    *(__nv_bfloat162*)(outhi + idx) = __nv_bfloat162(hx, hy);
                    *(__nv_bfloat162*)(outlo + idx) = __nv_bfloat162(lx, ly);
                }
            }
        }
    }
}

// ---------------------------------------------------------------------------
// Flash attention v3b (unchanged from R8): 256 threads, BR=128, BC=64,
// Q frags in regs, K via ldmatrix, V via ldmatrix.trans, P hi/lo bf16.
// ---------------------------------------------------------------------------
#define FV_K(st) ((st)*17408)
#define FV_V(st) (34816 + (st)*17408)
#define FV_SMEM_BYTES (69632*2)

__global__ __launch_bounds__(256) void flash_attn_v3(
    const __nv_bfloat16* __restrict__ Qhi, const __nv_bfloat16* __restrict__ Qlo,
    const __nv_bfloat16* __restrict__ Khi, const __nv_bfloat16* __restrict__ Klo,
    const __nv_bfloat16* __restrict__ Vhi, const __nv_bfloat16* __restrict__ Vlo,
    __nv_bfloat16* __restrict__ Chi, __nv_bfloat16* __restrict__ Clo)
{
    __nv_bfloat16* sm = (__nv_bfloat16*)sm_raw;
    const int tid = threadIdx.x, lane = tid & 31, w = tid >> 5;
    const int g = lane >> 2, tg = lane & 3;
    const int bh = blockIdx.y, b = bh >> 4, head = bh & 15;
    const int q0 = (NQ - 1 - (int)blockIdx.x) * 128;
    const size_t base = (size_t)bh * S_ * HD;
    const uint32_t sb = smem_u32(sm);
    const int nt = q0 / 64 + 2;

    const int sub   = lane & 7;
    const int halfb = (lane >> 3) & 1;
    const int grpb  = lane >> 4;

    auto issueKV = [&](int kt, int st) {
        const int k0 = kt * 64;
        const uint32_t kb = sb + FV_K(st) * 2;
        const uint32_t vb = sb + FV_V(st) * 2;
        #pragma unroll
        for (int p = 0; p < 4; p++) {
            const int ch = tid + p * 256;
            const int r = ch >> 4, c8 = (ch & 15) * 8;
            const uint32_t off = (uint32_t)(r * 136 + c8) * 2;
            const size_t go = base + (size_t)(k0 + r) * HD + c8;
            cp16(kb + off,          Khi + go);
            cp16(kb + 17408 + off,  Klo + go);
            cp16(vb + off,          Vhi + go);
            cp16(vb + 17408 + off,  Vlo + go);
        }
        cp_commit();
    };

    issueKV(0, 0);

    uint32_t qh[8][4], ql[8][4];
    {
        const size_t r0g = base + (size_t)(q0 + w * 16 + g) * HD;
        #pragma unroll
        for (int kk = 0; kk < 8; kk++) {
            const int c = kk * 16 + 2 * tg;
            qh[kk][0] = *(const uint32_t*)(Qhi + r0g + c);
            qh[kk][1] = *(const uint32_t*)(Qhi + r0g + 8 * HD + c);
            qh[kk][2] = *(const uint32_t*)(Qhi + r0g + c + 8);
            qh[kk][3] = *(const uint32_t*)(Qhi + r0g + 8 * HD + c + 8);
            ql[kk][0] = *(const uint32_t*)(Qlo + r0g + c);
            ql[kk][1] = *(const uint32_t*)(Qlo + r0g + 8 * HD + c);
            ql[kk][2] = *(const uint32_t*)(Qlo + r0g + c + 8);
            ql[kk][3] = *(const uint32_t*)(Qlo + r0g + 8 * HD + c + 8);
        }
    }

    float oacc[16][4] = {};
    float m0 = -1e30f, m1 = -1e30f, l0 = 0.f, l1 = 0.f;
    const int r0 = q0 + w * 16 + g;

    const uint32_t kfragoff = (uint32_t)((8 * grpb + sub) * 136 + halfb * 8) * 2;
    const uint32_t vfragoff = (uint32_t)((8 * halfb + sub) * 136 + 8 * grpb) * 2;

    for (int kt = 0; kt < nt; kt++) {
        const int st = kt & 1;
        __syncthreads();
        if (kt + 1 < nt) { issueKV(kt + 1, st ^ 1); cp_wait<1>(); }
        else             { cp_wait<0>(); }
        __syncthreads();

        float sacc[8][4];
        #pragma unroll
        for (int j = 0; j < 8; j++)
            sacc[j][0] = sacc[j][1] = sacc[j][2] = sacc[j][3] = 0.f;
        const uint32_t kbase = sb + FV_K(st) * 2 + kfragoff;
        #pragma unroll
        for (int kk = 0; kk < 8; kk++) {
            #pragma unroll
            for (int jp = 0; jp < 4; jp++) {
                uint32_t bh4[4], bl4[4];
                const uint32_t ka = kbase + (uint32_t)(16 * jp * 136 + kk * 16) * 2;
                ldsm4(bh4, ka);
                ldsm4(bl4, ka + 17408);
                mma16816(sacc[2*jp],   qh[kk], bh4);
                mma16816(sacc[2*jp+1], qh[kk], bh4 + 2);
                mma16816(sacc[2*jp],   qh[kk], bl4);
                mma16816(sacc[2*jp+1], qh[kk], bl4 + 2);
                mma16816(sacc[2*jp],   ql[kk], bh4);
                mma16816(sacc[2*jp+1], ql[kk], bh4 + 2);
            }
        }

        const int k0 = kt * 64;
        if (k0 + 63 > r0) {
            #pragma unroll
            for (int j = 0; j < 8; j++) {
                const int c = k0 + j * 8 + 2 * tg;
                if (c     > r0)     sacc[j][0] = -1e30f;
                if (c + 1 > r0)     sacc[j][1] = -1e30f;
                if (c     > r0 + 8) sacc[j][2] = -1e30f;
                if (c + 1 > r0 + 8) sacc[j][3] = -1e30f;
            }
        }

        float rx0 = -1e30f, rx1 = -1e30f;
        #pragma unroll
        for (int j = 0; j < 8; j++) {
            rx0 = fmaxf(rx0, fmaxf(sacc[j][0], sacc[j][1]));
            rx1 = fmaxf(rx1, fmaxf(sacc[j][2], sacc[j][3]));
        }
        rx0 = fmaxf(rx0, __shfl_xor_sync(0xffffffffu, rx0, 1));
        rx0 = fmaxf(rx0, __shfl_xor_sync(0xffffffffu, rx0, 2));
        rx1 = fmaxf(rx1, __shfl_xor_sync(0xffffffffu, rx1, 1));
        rx1 = fmaxf(rx1, __shfl_xor_sync(0xffffffffu, rx1, 2));
        const float mn0 = fmaxf(m0, rx0), mn1 = fmaxf(m1, rx1);
        const float c0 = __expf(m0 - mn0), c1 = __expf(m1 - mn1);

        uint32_t ph0[8], ph1[8], pl0[8], pl1[8];
        float sum0 = 0.f, sum1 = 0.f;
        #pragma unroll
        for (int j = 0; j < 8; j++) {
            float p00 = __expf(sacc[j][0] - mn0);
            float p01 = __expf(sacc[j][1] - mn0);
            float p10 = __expf(sacc[j][2] - mn1);
            float p11 = __expf(sacc[j][3] - mn1);
            sum0 += p00 + p01;  sum1 += p10 + p11;
            ph0[j] = packbf(p00, p01);
            ph1[j] = packbf(p10, p11);
            __nv_bfloat162 hA = *(__nv_bfloat162*)&ph0[j];
            __nv_bfloat162 hB = *(__nv_bfloat162*)&ph1[j];
            pl0[j] = packbf(p00 - __bfloat162float(hA.x), p01 - __bfloat162float(hA.y));
            pl1[j] = packbf(p10 - __bfloat162float(hB.x), p11 - __bfloat162float(hB.y));
        }
        sum0 += __shfl_xor_sync(0xffffffffu, sum0, 1);
        sum0 += __shfl_xor_sync(0xffffffffu, sum0, 2);
        sum1 += __shfl_xor_sync(0xffffffffu, sum1, 1);
        sum1 += __shfl_xor_sync(0xffffffffu, sum1, 2);
        l0 = l0 * c0 + sum0;  m0 = mn0;
        l1 = l1 * c1 + sum1;  m1 = mn1;
        #pragma unroll
        for (int jd = 0; jd < 16; jd++) {
            oacc[jd][0] *= c0; oacc[jd][1] *= c0;
            oacc[jd][2] *= c1; oacc[jd][3] *= c1;
        }

        const uint32_t vbase = sb + FV_V(st) * 2 + vfragoff;
        #pragma unroll
        for (int kk2 = 0; kk2 < 4; kk2++) {
            uint32_t a_h[4] = { ph0[2*kk2], ph1[2*kk2], ph0[2*kk2+1], ph1[2*kk2+1] };
            uint32_t a_l[4] = { pl0[2*kk2], pl1[2*kk2], pl0[2*kk2+1], pl1[2*kk2+1] };
            #pragma unroll
            for (int jdp = 0; jdp < 8; jdp++) {
                uint32_t vh4[4], vl4[4];
                const uint32_t va = vbase + (uint32_t)(16 * kk2 * 136 + 16 * jdp) * 2;
                ldsm4t(vh4, va);
                ldsm4t(vl4, va + 17408);
                mma16816(oacc[2*jdp],   a_h, vh4);
                mma16816(oacc[2*jdp+1], a_h, vh4 + 2);
                mma16816(oacc[2*jdp],   a_l, vh4);
                mma16816(oacc[2*jdp+1], a_l, vh4 + 2);
                mma16816(oacc[2*jdp],   a_h, vl4);
                mma16816(oacc[2*jdp+1], a_h, vl4 + 2);
            }
        }
    }

    const float i0 = 1.f / l0, i1 = 1.f / l1;
    #pragma unroll
    for (int jd = 0; jd < 16; jd++) {
        const int d = jd * 8 + 2 * tg;
        const float o00 = oacc[jd][0] * i0, o01 = oacc[jd][1] * i0;
        const float o10 = oacc[jd][2] * i1, o11 = oacc[jd][3] * i1;
        const size_t idx0 = ((size_t)b * S_ + r0)     * H_ + head * HD + d;
        const size_t idx1 = ((size_t)b * S_ + r0 + 8) * H_ + head * HD + d;
        __nv_bfloat16 hx, hy, lx, ly;
        split1(o00, hx, lx); split1(o01, hy, ly);
        *(__nv_bfloat162*)(Chi + idx0) = __nv_bfloat162(hx, hy);
        *(__nv_bfloat162*)(Clo + idx0) = __nv_bfloat162(lx, ly);
        split1(o10, hx, lx); split1(o11, hy, ly);
        *(__nv_bfloat162*)(Chi + idx1) = __nv_bfloat162(hx, hy);
        *(__nv_bfloat162*)(Clo + idx1) = __nv_bfloat162(lx, ly);
    }
}

// ---------------------------------------------------------------------------
extern "C" void kernel_launch(void* const* d_in, const int* in_sizes, int n_in,
                              void* d_out, int out_size)
{
    const float* x  = (const float*)d_in[0];
    const float* wq = (const float*)d_in[1];
    const float* bq = (const float*)d_in[2];
    const float* wk = (const float*)d_in[3];
    const float* bk = (const float*)d_in[4];
    const float* wv = (const float*)d_in[5];
    const float* bv = (const float*)d_in[6];
    const float* wo = (const float*)d_in[7];
    const float* bo = (const float*)d_in[8];
    float* out = (float*)d_out;

    __nv_bfloat16 *xhi, *xlo, *whi, *wlo;
    __nv_bfloat16 *qhi, *qlo, *khi, *klo, *vhi, *vlo, *chi, *clo;
    cudaGetSymbolAddress((void**)&xhi, g_xhi);
    cudaGetSymbolAddress((void**)&xlo, g_xlo);
    cudaGetSymbolAddress((void**)&whi, g_whi);
    cudaGetSymbolAddress((void**)&wlo, g_wlo);
    cudaGetSymbolAddress((void**)&qhi, g_qhi);
    cudaGetSymbolAddress((void**)&qlo, g_qlo);
    cudaGetSymbolAddress((void**)&khi, g_khi);
    cudaGetSymbolAddress((void**)&klo, g_klo);
    cudaGetSymbolAddress((void**)&vhi, g_vhi);
    cudaGetSymbolAddress((void**)&vlo, g_vlo);
    cudaGetSymbolAddress((void**)&chi, g_chi);
    cudaGetSymbolAddress((void**)&clo, g_clo);

    static bool attr_set = false;
    if (!attr_set) {
        cudaFuncSetAttribute(gemm_bf16x3<0>, cudaFuncAttributeMaxDynamicSharedMemorySize, GEMM_SMEM_BYTES);
        cudaFuncSetAttribute(gemm_bf16x3<1>, cudaFuncAttributeMaxDynamicSharedMemorySize, GEMM_SMEM_BYTES);
        cudaFuncSetAttribute(flash_attn_v3, cudaFuncAttributeMaxDynamicSharedMemorySize, FV_SMEM_BYTES);
        attr_set = true;
    }

    const float qscale = 0.08838834764831845f;   // 1/sqrt(128)

    split_bf16<<<1024, 256>>>(x, xhi, xlo, M_*H_/4);
    split_bf16_w4<<<dim3(256, 4), 256>>>(wq, wk, wv, wo, whi, wlo, H_*H_/4);

    // Fused QKV projection: blockIdx.z in {0,1,2} selects weight/bias/output
    dim3 gqkv(H_/128, M_/128, 3);   // (16, 32, 3)
    gemm_bf16x3<0><<<gqkv, 256, GEMM_SMEM_BYTES>>>(
        xhi, xlo, whi, wlo, bq, bk, bv, qscale, nullptr,
        qhi, qlo, khi, klo, vhi, vlo);

    dim3 gf(NQ, B_*NH);   // (16, 32)
    flash_attn_v3<<<gf, 256, FV_SMEM_BYTES>>>(qhi, qlo, khi, klo, vhi, vlo, chi, clo);

    // Output projection (weight slot 3)
    dim3 gg(H_/128, M_/128);
    gemm_bf16x3<1><<<gg, 256, GEMM_SMEM_BYTES>>>(
        chi, clo, whi + 3*(size_t)H_*H_, wlo + 3*(size_t)H_*H_,
        bo, bo, bo, 1.f, out,
        nullptr, nullptr, nullptr, nullptr, nullptr, nullptr);
}